// round 10
// baseline (speedup 1.0000x reference)
#include <cuda_runtime.h>
#include <cuda_bf16.h>
#include <cstdint>
#include <cstddef>

#define BATCH 8
#define SEQ   2048
#define DIM   768
#define MTOT  (BATCH*SEQ)   // 16384

#if defined(__CUDA_ARCH_FEAT_SM103_ALL) || defined(__CUDA_ARCH_FEAT_SM100_ALL)
#define ATHENA_TCGEN05 1
#endif

// ---------------- scratch (no dynamic allocation allowed) -------------------
__device__ __nv_bfloat16 g_X1b[(size_t)MTOT*DIM];
__device__ __nv_bfloat16 g_X2b[(size_t)MTOT*DIM];
__device__ __nv_bfloat16 g_Q  [(size_t)MTOT*DIM];
__device__ __nv_bfloat16 g_K  [(size_t)MTOT*DIM];
__device__ __nv_bfloat16 g_Wqt[(size_t)DIM*DIM];
__device__ __nv_bfloat16 g_Wkt[(size_t)DIM*DIM];

// ---------------- helpers ----------------------------------------------------
__device__ __forceinline__ uint32_t smem_u32(const void* p) {
    uint32_t a;
    asm("{ .reg .u64 t; cvta.to.shared.u64 t, %1; cvt.u32.u64 %0, t; }"
        : "=r"(a) : "l"(p));
    return a;
}
__device__ __forceinline__ void ldsm_x4(uint32_t* r, uint32_t addr) {
    asm volatile("ldmatrix.sync.aligned.m8n8.x4.shared.b16 {%0,%1,%2,%3}, [%4];"
                 : "=r"(r[0]), "=r"(r[1]), "=r"(r[2]), "=r"(r[3]) : "r"(addr));
}
__device__ __forceinline__ void mma_bf16(float* c, const uint32_t* a,
                                         uint32_t b0, uint32_t b1) {
    asm volatile(
        "mma.sync.aligned.m16n8k16.row.col.f32.bf16.bf16.f32 "
        "{%0,%1,%2,%3}, {%4,%5,%6,%7}, {%8,%9}, {%0,%1,%2,%3};"
        : "+f"(c[0]), "+f"(c[1]), "+f"(c[2]), "+f"(c[3])
        : "r"(a[0]), "r"(a[1]), "r"(a[2]), "r"(a[3]), "r"(b0), "r"(b1));
}
__device__ __forceinline__ float fast_tanh(float x) {
    float y; asm("tanh.approx.f32 %0, %1;" : "=f"(y) : "f"(x)); return y;
}
#define CP16(dst, src) \
    asm volatile("cp.async.cg.shared.global [%0], [%1], 16;" :: "r"(dst), "l"(src))
#define CP_COMMIT() asm volatile("cp.async.commit_group;" ::: "memory")
#define CP_WAIT(N)  asm volatile("cp.async.wait_group %0;" :: "n"(N) : "memory")

// mma.sync-path SMEM tile: 128 rows x 64 bf16 padded to 144 B/row
#define SROW2 144
#define TILE2 (128*SROW2)      // 18432 bytes
#define NCH   12               // 768 / 64
#define GTOT  (16*NCH)         // 192 chunks (16 s-tiles x 12 k-chunks)

// R7 CHUNK_MMA (proven): B-fragment ping-pong prefetch.
#define CHUNK_MMA(AsX, BsX) do { \
    _Pragma("unroll") \
    for (int ks = 0; ks < 4; ks++) { \
        uint32_t a0[4], a1[4], bmA[4], bmB[4]; \
        ldsm_x4(a0,  (AsX) + aoff0 + ks * 32); \
        ldsm_x4(a1,  (AsX) + aoff1 + ks * 32); \
        ldsm_x4(bmA, (BsX) + boff + ks * 32); \
        _Pragma("unroll") \
        for (int np = 0; np < 4; np++) { \
            uint32_t* bc = (np & 1) ? bmB : bmA; \
            uint32_t* bn_ = (np & 1) ? bmA : bmB; \
            if (np < 3) \
                ldsm_x4(bn_, (BsX) + boff + (np + 1) * (16 * SROW2) + ks * 32); \
            mma_bf16(acc[0][np*2],   a0, bc[0], bc[2]); \
            mma_bf16(acc[0][np*2+1], a0, bc[1], bc[3]); \
            mma_bf16(acc[1][np*2],   a1, bc[0], bc[2]); \
            mma_bf16(acc[1][np*2+1], a1, bc[1], bc[3]); \
        } \
    } \
} while (0)

// ---------------- tcgen05 helpers (device-guarded) ----------------------------
#ifdef ATHENA_TCGEN05
#define SWZ(o) ((o) ^ (((o) >> 3) & 0x70))
#define MBARRIER_INIT(addr, cnt) \
    asm volatile("mbarrier.init.shared.b64 [%0], %1;" :: "r"(addr), "r"(cnt) : "memory")
#define MBARRIER_WAIT_PARITY(mbar, par) do { \
    uint32_t _m = (uint32_t)(mbar), _p = (uint32_t)(par), _d; \
    asm volatile("{\n\t.reg .pred p;\n\t" \
        "mbarrier.try_wait.parity.acquire.cta.shared::cta.b64 p, [%1], %2;\n\t" \
        "selp.b32 %0, 1, 0, p;\n\t}" : "=r"(_d) : "r"(_m), "r"(_p) : "memory"); \
    if (!_d) { \
        asm volatile("{\n\t.reg .pred P1;\n\t" \
            "WL_%=:\n\t" \
            "mbarrier.try_wait.parity.acquire.cta.shared::cta.b64 P1, [%0], %1, 0x989680;\n\t" \
            "@P1 bra.uni WD_%=;\n\t" \
            "bra.uni WL_%=;\n\t" \
            "WD_%=:\n\t}" :: "r"(_m), "r"(_p) : "memory"); \
    } \
} while (0)
#define TCGEN05_ALLOC(sr, n) \
    asm volatile("tcgen05.alloc.cta_group::1.sync.aligned.shared::cta.b32 [%0], %1;" \
                 :: "r"((uint32_t)(sr)), "r"((uint32_t)(n)) : "memory")
#define TCGEN05_DEALLOC(t, n) \
    asm volatile("tcgen05.dealloc.cta_group::1.sync.aligned.b32 %0, %1;" :: "r"(t), "r"(n))
#define TCGEN05_RELINQ() \
    asm volatile("tcgen05.relinquish_alloc_permit.cta_group::1.sync.aligned;")
#define TCGEN05_COMMIT(mbar) \
    asm volatile("tcgen05.commit.cta_group::1.mbarrier::arrive::one.shared::cluster.b64 [%0];" \
                 :: "r"((uint32_t)(mbar)) : "memory")
#define TCGEN05_FENCE_BEFORE() asm volatile("tcgen05.fence::before_thread_sync;" ::: "memory")
#define TCGEN05_FENCE_AFTER()  asm volatile("tcgen05.fence::after_thread_sync;" ::: "memory")
#define TCGEN05_WAIT_LD()      asm volatile("tcgen05.wait::ld.sync.aligned;" ::: "memory")
#define FENCE_ASYNC_SHARED()   asm volatile("fence.proxy.async.shared::cta;" ::: "memory")
#define TCGEN05_LD_X32(r, ta) \
    asm volatile( \
        "tcgen05.ld.sync.aligned.32x32b.x32.b32 " \
        "{%0, %1, %2, %3, %4, %5, %6, %7, " \
        " %8, %9, %10, %11, %12, %13, %14, %15, " \
        " %16, %17, %18, %19, %20, %21, %22, %23, " \
        " %24, %25, %26, %27, %28, %29, %30, %31}, [%32];" \
        : "=r"((r)[0]),  "=r"((r)[1]),  "=r"((r)[2]),  "=r"((r)[3]), \
          "=r"((r)[4]),  "=r"((r)[5]),  "=r"((r)[6]),  "=r"((r)[7]), \
          "=r"((r)[8]),  "=r"((r)[9]),  "=r"((r)[10]), "=r"((r)[11]), \
          "=r"((r)[12]), "=r"((r)[13]), "=r"((r)[14]), "=r"((r)[15]), \
          "=r"((r)[16]), "=r"((r)[17]), "=r"((r)[18]), "=r"((r)[19]), \
          "=r"((r)[20]), "=r"((r)[21]), "=r"((r)[22]), "=r"((r)[23]), \
          "=r"((r)[24]), "=r"((r)[25]), "=r"((r)[26]), "=r"((r)[27]), \
          "=r"((r)[28]), "=r"((r)[29]), "=r"((r)[30]), "=r"((r)[31]) \
        : "r"(ta))

__device__ __forceinline__ uint32_t elect_one() {
    uint32_t pred;
    asm volatile("{\n\t.reg .pred p;\n\telect.sync _|p, 0xFFFFFFFF;\n\t"
                 "selp.b32 %0, 1, 0, p;\n\t}" : "=r"(pred));
    return pred;
}
// SW128 K-major descriptor: layout=2, version=1, SBO=64, LBO=1
__device__ __forceinline__ uint64_t make_desc(uint32_t addr) {
    return ((uint64_t)2 << 61) | ((uint64_t)1 << 46) | ((uint64_t)64 << 32)
         | ((uint64_t)1 << 16) | ((uint64_t)(addr >> 4) & 0x3FFF);
}
// kind::f16 idesc: f32 acc, bf16 a/b, N=128, M=128
#define IDESC_T 0x8200490u
__device__ __forceinline__ void mma_f16_ss(uint32_t d, uint64_t ad, uint64_t bd,
                                           bool accum) {
    uint32_t en = accum ? 1u : 0u;
    asm volatile(
        "{\n\t.reg .pred p;\n\t"
        "setp.ne.u32 p, %5, 0;\n\t"
        "tcgen05.mma.cta_group::1.kind::f16 [%0], %1, %2, %3, {%4, %4, %4, %4}, p;\n\t}"
        :: "r"(d), "l"(ad), "l"(bd), "r"(IDESC_T), "r"(0u), "r"(en)
        : "memory");
}
#endif // ATHENA_TCGEN05

// ---------------------------------------------------------------------------
// small elementwise kernels
// ---------------------------------------------------------------------------
__global__ void convert_bf16_2(const float* __restrict__ x1, const float* __restrict__ x2,
                               __nv_bfloat16* __restrict__ y1, __nv_bfloat16* __restrict__ y2)
{
    const float* x = blockIdx.z ? x2 : x1;
    __nv_bfloat16* y = blockIdx.z ? y2 : y1;
    const size_t i = ((size_t)blockIdx.x * blockDim.x + threadIdx.x) * 8;
    float4 v0 = *(const float4*)(x + i);
    float4 v1 = *(const float4*)(x + i + 4);
    __nv_bfloat162 a = __floats2bfloat162_rn(v0.x, v0.y);
    __nv_bfloat162 b = __floats2bfloat162_rn(v0.z, v0.w);
    __nv_bfloat162 c = __floats2bfloat162_rn(v1.x, v1.y);
    __nv_bfloat162 d = __floats2bfloat162_rn(v1.z, v1.w);
    uint4 st; st.x = *(uint32_t*)&a; st.y = *(uint32_t*)&b;
    st.z = *(uint32_t*)&c; st.w = *(uint32_t*)&d;
    *(uint4*)(y + i) = st;
}

__global__ void transpose_bf16_2(const float* __restrict__ W1, const float* __restrict__ W2,
                                 __nv_bfloat16* __restrict__ T1, __nv_bfloat16* __restrict__ T2)
{
    const float* W = blockIdx.z ? W2 : W1;
    __nv_bfloat16* Wt = blockIdx.z ? T2 : T1;
    __shared__ float t[32][33];
    int tx = threadIdx.x, ty = threadIdx.y;
    int bk = blockIdx.y * 32, bn = blockIdx.x * 32;
#pragma unroll
    for (int j = 0; j < 4; j++)
        t[ty + j * 8][tx] = W[(size_t)(bk + ty + j * 8) * DIM + bn + tx];
    __syncthreads();
#pragma unroll
    for (int j = 0; j < 4; j++)
        Wt[(size_t)(bn + ty + j * 8) * DIM + bk + tx] = __float2bfloat16(t[tx][ty + j * 8]);
}

// ---------------------------------------------------------------------------
// Phase 1 (merged Q & K via blockIdx.z): mma.sync path (proven).
// ---------------------------------------------------------------------------
#define P1_SMEM (6*TILE2 + 512)

__global__ void __launch_bounds__(256, 2)
gemm_bias_mma(const __nv_bfloat16* __restrict__ A1, const __nv_bfloat16* __restrict__ A2,
              const __nv_bfloat16* __restrict__ B1, const __nv_bfloat16* __restrict__ B2,
              const float* __restrict__ bias1, const float* __restrict__ bias2,
              __nv_bfloat16* __restrict__ O1, __nv_bfloat16* __restrict__ O2)
{
    extern __shared__ __align__(16) char smem[];
    const uint32_t sb = smem_u32(smem);
    const int tid = threadIdx.x, lane = tid & 31, wid = tid >> 5;
    const int wm = wid >> 1, wn = wid & 1;
    const int n0 = blockIdx.x * 128, m0 = blockIdx.y * 128;
    const int z = blockIdx.z;

    const __nv_bfloat16* A  = z ? A2 : A1;
    const __nv_bfloat16* Bt = z ? B2 : B1;
    const float* bias       = z ? bias2 : bias1;
    __nv_bfloat16* Out      = z ? O2 : O1;

    float* bias_s = (float*)(smem + 6*TILE2);
    if (tid < 128) bias_s[tid] = bias[n0 + tid];

    const __nv_bfloat16* Ag = A  + (size_t)m0 * DIM;
    const __nv_bfloat16* Bg = Bt + (size_t)n0 * DIM;

    const int br = tid >> 3, bsg = tid & 7;
    const uint32_t lane_off = (uint32_t)(lane & 15) * SROW2 + (uint32_t)(lane >> 4) * 16;
    const uint32_t aoff0 = (uint32_t)(wm * 32) * SROW2 + lane_off;
    const uint32_t aoff1 = aoff0 + 16 * SROW2;
    const uint32_t boff  = (uint32_t)(wn * 64) * SROW2 + lane_off;

    float acc[2][8][4];
#pragma unroll
    for (int i = 0; i < 2; i++)
#pragma unroll
        for (int j = 0; j < 8; j++)
#pragma unroll
            for (int q = 0; q < 4; q++) acc[i][j][q] = 0.f;

#define GEMM_ISSUE(cc) do { \
        const int _bf = (cc) % 3; \
        const uint32_t _da = sb + _bf * TILE2; \
        const uint32_t _db = sb + 3*TILE2 + _bf * TILE2; \
        _Pragma("unroll") \
        for (int _p = 0; _p < 4; _p++) { \
            const int _r = br + _p * 32; \
            CP16(_da + _r * SROW2 + bsg * 16, \
                 (const char*)(Ag + (size_t)_r * DIM + (cc) * 64 + bsg * 8)); \
            CP16(_db + _r * SROW2 + bsg * 16, \
                 (const char*)(Bg + (size_t)_r * DIM + (cc) * 64 + bsg * 8)); \
        } \
        CP_COMMIT(); \
    } while (0)

    GEMM_ISSUE(0);
    GEMM_ISSUE(1);

    for (int c = 0; c < NCH; c++) {
        if (c < NCH - 1) CP_WAIT(1); else CP_WAIT(0);
        __syncthreads();
        if (c + 2 < NCH) GEMM_ISSUE(c + 2);

        const uint32_t As = sb + (c % 3) * TILE2;
        const uint32_t Bs = sb + 3*TILE2 + (c % 3) * TILE2;
        CHUNK_MMA(As, Bs);
    }
#undef GEMM_ISSUE

#pragma unroll
    for (int mt = 0; mt < 2; mt++) {
        const int m = m0 + wm * 32 + mt * 16 + (lane >> 2);
#pragma unroll
        for (int nt = 0; nt < 8; nt++) {
            const int nl = wn * 64 + nt * 8 + (lane & 3) * 2;
            const float b0 = bias_s[nl], b1 = bias_s[nl + 1];
            __nv_bfloat162 p0 = __floats2bfloat162_rn(acc[mt][nt][0] + b0, acc[mt][nt][1] + b1);
            __nv_bfloat162 p1 = __floats2bfloat162_rn(acc[mt][nt][2] + b0, acc[mt][nt][3] + b1);
            *(__nv_bfloat162*)(Out + (size_t)m       * DIM + n0 + nl) = p0;
            *(__nv_bfloat162*)(Out + (size_t)(m + 8) * DIM + n0 + nl) = p1;
        }
    }
}

// ---------------------------------------------------------------------------
// Phase 2: per (t-block 128, batch): 16 s-tiles of 128, writes out directly.
// tcgen05 body: 5-slot Q/K ring, issue-ahead 4, D ping-pong in TMEM,
// register num/den accumulation. Fallback: mma.sync (R7 structure).
// ---------------------------------------------------------------------------
#define RING  5
#define TS    16384
#define P2_SMEM (2048 + 2*RING*TS)   // 165,888

__global__ void __launch_bounds__(256, 1)
attn_mma(const __nv_bfloat16* __restrict__ Q, const __nv_bfloat16* __restrict__ K,
         float* __restrict__ out)
{
    extern __shared__ __align__(16) char smem[];
    const uint32_t sb = smem_u32(smem);
    const int tid = threadIdx.x, lane = tid & 31, wid = tid >> 5;
    const int t0 = blockIdx.x * 128, b = blockIdx.y;
    const __nv_bfloat16* Kg    = K + ((size_t)b * SEQ + t0) * DIM;
    const __nv_bfloat16* Qbase = Q + (size_t)b * SEQ * DIM;
    const int br = tid >> 3, bsg = tid & 7;

#ifdef ATHENA_TCGEN05
    // ======================= tcgen05 body =======================
    // SMEM: [0] tmem ptr | [8..48) slot mbars x5 | [48..64) tile mbars x2
    //       [1024) num | [1536) den | [2048) Q ring 5xTS | [+5*TS) K ring 5xTS
    float* num_sh = (float*)(smem + 1024);
    float* den_sh = (float*)(smem + 1536);
    const uint32_t MB = sb + 8;
    const int half = wid >> 2;

    if (wid == 0) TCGEN05_ALLOC(sb + 0, 256);
    if (tid == 0) {
#pragma unroll
        for (int s = 0; s < RING; s++) MBARRIER_INIT(MB + 8 * s, 1);
        MBARRIER_INIT(MB + 40, 1); MBARRIER_INIT(MB + 48, 1);
    }
    if (tid < 128) { num_sh[tid] = 0.f; den_sh[tid] = 0.f; }
    __syncthreads();
    uint32_t tmem;
    asm volatile("ld.shared.b32 %0, [%1];" : "=r"(tmem) : "r"(sb + 0));
    if (wid == 0) TCGEN05_RELINQ();

    int phs[RING] = {0, 0, 0, 0, 0};
    int pht[2] = {0, 0};
    float rnum[2] = {0.f, 0.f}, rden[2] = {0.f, 0.f};

#define TQ(bf) (sb + 2048 + (bf) * TS)
#define TK(bf) (sb + 2048 + RING * TS + (bf) * TS)
#define ATTN_ISSUE_T(gg) do { \
        const int _st = (gg) / NCH, _cc = (gg) % NCH, _bf = (gg) % RING; \
        const __nv_bfloat16* _Qp = Qbase + (size_t)(_st * 128) * DIM + _cc * 64; \
        const __nv_bfloat16* _Kp = Kg + _cc * 64; \
        _Pragma("unroll") \
        for (int _p = 0; _p < 4; _p++) { \
            const int _r = br + _p * 32; \
            const uint32_t _sw = SWZ((uint32_t)(_r * 128 + bsg * 16)); \
            CP16(TQ(_bf) + _sw, (const char*)(_Qp + (size_t)_r * DIM + bsg * 8)); \
            CP16(TK(_bf) + _sw, (const char*)(_Kp + (size_t)_r * DIM + bsg * 8)); \
        } \
        CP_COMMIT(); \
    } while (0)

    // epilogue for finished s-tile ti (D buffer ti&1): reduce into registers
#define EPILOGUE_T(ti) do { \
        const int _db = (ti) & 1; \
        MBARRIER_WAIT_PARITY(MB + 40 + 8 * _db, pht[_db]); pht[_db] ^= 1; \
        TCGEN05_FENCE_AFTER(); \
        uint32_t rr[64]; \
        TCGEN05_LD_X32(rr,      tmem + _db * 128 + half * 64); \
        TCGEN05_LD_X32(rr + 32, tmem + _db * 128 + half * 64 + 32); \
        TCGEN05_WAIT_LD(); \
        TCGEN05_FENCE_BEFORE(); \
        _Pragma("unroll 8") \
        for (int cc = 0; cc < 64; cc++) { \
            float qk = __uint_as_float(rr[cc]); \
            float e  = __expf(fast_tanh(qk)); \
            float nv = e * qk; \
            _Pragma("unroll") \
            for (int o = 16; o; o >>= 1) { \
                nv += __shfl_xor_sync(0xFFFFFFFFu, nv, o); \
                e  += __shfl_xor_sync(0xFFFFFFFFu, e,  o); \
            } \
            if ((cc & 31) == lane) { rnum[cc >> 5] += nv; rden[cc >> 5] += e; } \
        } \
    } while (0)

    ATTN_ISSUE_T(0); ATTN_ISSUE_T(1); ATTN_ISSUE_T(2); ATTN_ISSUE_T(3);

    for (int g = 0; g < GTOT; g++) {
        if (g < GTOT - 4)      CP_WAIT(3);
        else if (g == GTOT - 4) CP_WAIT(3);
        else if (g == GTOT - 3) CP_WAIT(2);
        else if (g == GTOT - 2) CP_WAIT(1);
        else                    CP_WAIT(0);
        __syncthreads();

        if (g + 4 < GTOT) {
            if (g >= 1) {   // slot (g+4)%RING was MMA'd as chunk g-1; wait drain
                const int rbs = (g + 4) % RING;
                MBARRIER_WAIT_PARITY(MB + 8 * rbs, phs[rbs]);
                phs[rbs] ^= 1;
            }
            ATTN_ISSUE_T(g + 4);
        }
        if (wid == 0) {
            FENCE_ASYNC_SHARED();
            if (elect_one()) {
                const int bf = g % RING;
                const int ti = g / NCH;
                uint64_t qd = make_desc(TQ(bf));
                uint64_t kd = make_desc(TK(bf));
                const uint32_t d = tmem + (ti & 1) * 128;
#pragma unroll
                for (int s = 0; s < 4; s++)
                    mma_f16_ss(d, qd + s * 2, kd + s * 2, !((g % NCH) == 0 && s == 0));
                TCGEN05_COMMIT(MB + 8 * bf);
                if ((g % NCH) == NCH - 1) TCGEN05_COMMIT(MB + 40 + 8 * (ti & 1));
            }
        }
        // epilogue for previous tile, after first MMA of this tile is in flight
        if ((g % NCH) == 0 && g > 0) EPILOGUE_T(g / NCH - 1);
    }
    EPILOGUE_T(15);

    // combine register partials across the 4 warps of each half
    atomicAdd(&num_sh[half * 64 + lane],      rnum[0]);
    atomicAdd(&num_sh[half * 64 + 32 + lane], rnum[1]);
    atomicAdd(&den_sh[half * 64 + lane],      rden[0]);
    atomicAdd(&den_sh[half * 64 + 32 + lane], rden[1]);
    __syncthreads();
    if (tid < 128)
        out[(size_t)b * SEQ + t0 + tid] = num_sh[tid] / (den_sh[tid] + 1e-7f);
    __syncthreads();
    if (wid == 0) TCGEN05_DEALLOC(tmem, 256);
#undef ATTN_ISSUE_T
#undef EPILOGUE_T
#undef TQ
#undef TK

#else
    // ======================= mma.sync fallback (R7 structure) ====================
    float* num_sh = (float*)(smem + 1024);
    float* den_sh = num_sh + 128;
    char* ring = smem + 2048;
    const int wm = wid >> 1, wn = wid & 1;

    if (tid < 128) { num_sh[tid] = 0.f; den_sh[tid] = 0.f; }

    const uint32_t lane_off = (uint32_t)(lane & 15) * SROW2 + (uint32_t)(lane >> 4) * 16;
    const uint32_t aoff0 = (uint32_t)(wm * 32) * SROW2 + lane_off;
    const uint32_t aoff1 = aoff0 + 16 * SROW2;
    const uint32_t boff  = (uint32_t)(wn * 64) * SROW2 + lane_off;
    const uint32_t rg = sb + 2048;

    float acc[2][8][4];
#pragma unroll
    for (int i = 0; i < 2; i++)
#pragma unroll
        for (int j = 0; j < 8; j++)
#pragma unroll
            for (int q = 0; q < 4; q++) acc[i][j][q] = 0.f;

#define ATTN_ISSUE(gg) do { \
        const int _st = (gg) / NCH, _cc = (gg) % NCH, _bf = (gg) % 3; \
        const __nv_bfloat16* _Qp = Qbase + (size_t)(_st * 128) * DIM + _cc * 64; \
        const __nv_bfloat16* _Kp = Kg + _cc * 64; \
        const uint32_t _dq = rg + _bf * TILE2; \
        const uint32_t _dk = rg + 3*TILE2 + _bf * TILE2; \
        _Pragma("unroll") \
        for (int _p = 0; _p < 4; _p++) { \
            const int _r = br + _p * 32; \
            CP16(_dq + _r * SROW2 + bsg * 16, (const char*)(_Qp + (size_t)_r * DIM + bsg * 8)); \
            CP16(_dk + _r * SROW2 + bsg * 16, (const char*)(_Kp + (size_t)_r * DIM + bsg * 8)); \
        } \
        CP_COMMIT(); \
    } while (0)

    ATTN_ISSUE(0);
    ATTN_ISSUE(1);
    __syncthreads();

    for (int g = 0; g < GTOT; g++) {
        if (g < GTOT - 1) CP_WAIT(1); else CP_WAIT(0);
        __syncthreads();
        if (g + 2 < GTOT) ATTN_ISSUE(g + 2);

        const uint32_t As = rg + (g % 3) * TILE2;
        const uint32_t Bs = rg + 3*TILE2 + (g % 3) * TILE2;
        CHUNK_MMA(As, Bs);

        if ((g % NCH) == NCH - 1) {
#pragma unroll
            for (int nt = 0; nt < 8; nt++) {
                float vn0 = 0.f, vn1 = 0.f, vd0 = 0.f, vd1 = 0.f;
#pragma unroll
                for (int mt = 0; mt < 2; mt++) {
                    const float q0 = acc[mt][nt][0], q1 = acc[mt][nt][1];
                    const float q2 = acc[mt][nt][2], q3 = acc[mt][nt][3];
                    const float e0 = __expf(fast_tanh(q0));
                    const float e1 = __expf(fast_tanh(q1));
                    const float e2 = __expf(fast_tanh(q2));
                    const float e3 = __expf(fast_tanh(q3));
                    vn0 += e0 * q0 + e2 * q2;  vd0 += e0 + e2;
                    vn1 += e1 * q1 + e3 * q3;  vd1 += e1 + e3;
                }
#pragma unroll
                for (int o = 4; o <= 16; o <<= 1) {
                    vn0 += __shfl_xor_sync(0xFFFFFFFFu, vn0, o);
                    vn1 += __shfl_xor_sync(0xFFFFFFFFu, vn1, o);
                    vd0 += __shfl_xor_sync(0xFFFFFFFFu, vd0, o);
                    vd1 += __shfl_xor_sync(0xFFFFFFFFu, vd1, o);
                }
                if (lane < 4) {
                    const int col = wn * 64 + nt * 8 + lane * 2;
                    atomicAdd(&num_sh[col],     vn0);
                    atomicAdd(&num_sh[col + 1], vn1);
                    atomicAdd(&den_sh[col],     vd0);
                    atomicAdd(&den_sh[col + 1], vd1);
                }
            }
#pragma unroll
            for (int i = 0; i < 2; i++)
#pragma unroll
                for (int j = 0; j < 8; j++)
#pragma unroll
                    for (int q = 0; q < 4; q++) acc[i][j][q] = 0.f;
        }
    }
    __syncthreads();
    if (tid < 128)
        out[(size_t)b * SEQ + t0 + tid] = num_sh[tid] / (den_sh[tid] + 1e-7f);
#undef ATTN_ISSUE
#endif
}

// ---------------------------------------------------------------------------
extern "C" void kernel_launch(void* const* d_in, const int* in_sizes, int n_in,
                              void* d_out, int out_size)
{
    const float* x1 = (const float*)d_in[0];
    const float* x2 = (const float*)d_in[1];
    const float* Wq = (const float*)d_in[2];
    const float* bq = (const float*)d_in[3];
    const float* Wk = (const float*)d_in[4];
    const float* bk = (const float*)d_in[5];
    float* out = (float*)d_out;

    __nv_bfloat16 *X1b, *X2b, *Qp, *Kp, *Wqt, *Wkt;
    cudaGetSymbolAddress((void**)&X1b, g_X1b);
    cudaGetSymbolAddress((void**)&X2b, g_X2b);
    cudaGetSymbolAddress((void**)&Qp,  g_Q);
    cudaGetSymbolAddress((void**)&Kp,  g_K);
    cudaGetSymbolAddress((void**)&Wqt, g_Wqt);
    cudaGetSymbolAddress((void**)&Wkt, g_Wkt);

    cudaFuncSetAttribute(gemm_bias_mma, cudaFuncAttributeMaxDynamicSharedMemorySize, P1_SMEM);
    cudaFuncSetAttribute(attn_mma,      cudaFuncAttributeMaxDynamicSharedMemorySize, P2_SMEM);

    const int nconv = (int)(((size_t)MTOT * DIM / 8) / 256);   // 6144 blocks
    convert_bf16_2<<<dim3(nconv, 1, 2), 256>>>(x1, x2, X1b, X2b);

    dim3 tgrid(DIM / 32, DIM / 32, 2);
    transpose_bf16_2<<<tgrid, dim3(32, 8)>>>(Wq, Wk, Wqt, Wkt);

    dim3 ggrid(DIM / 128, MTOT / 128, 2);   // (6, 128, 2) = 1536 CTAs
    gemm_bias_mma<<<ggrid, 256, P1_SMEM>>>(X1b, X2b, Wqt, Wkt, bq, bk, Qp, Kp);

    dim3 agrid(SEQ / 128, BATCH);           // (16, 8) = 128 CTAs
    attn_mma<<<agrid, 256, P2_SMEM>>>(Qp, Kp, out);
}

// round 11
// speedup vs baseline: 1.6843x; 1.6843x over previous
#include <cuda_runtime.h>
#include <cuda_bf16.h>
#include <cstdint>
#include <cstddef>

#define BATCH 8
#define SEQ   2048
#define DIM   768
#define MTOT  (BATCH*SEQ)   // 16384
#define NCH   12            // 768 / 64 k-chunks
#define TILE_BYTES 16384    // one (128-row x 64-k) bf16 tile, SW128-swizzled
#define TILE_ELEMS 8192

// ---------------- scratch (no dynamic allocation allowed) -------------------
// All operand buffers use a blocked layout: [tile(128 rows)][chunk(64 k)] of
// contiguous 16KB SW128-swizzled tiles, so loads are single bulk copies.
__device__ __align__(256) __nv_bfloat16 g_X1b[(size_t)MTOT*DIM];
__device__ __align__(256) __nv_bfloat16 g_X2b[(size_t)MTOT*DIM];
__device__ __align__(256) __nv_bfloat16 g_Q  [(size_t)MTOT*DIM];
__device__ __align__(256) __nv_bfloat16 g_K  [(size_t)MTOT*DIM];
__device__ __align__(256) __nv_bfloat16 g_Wqt[(size_t)DIM*DIM];
__device__ __align__(256) __nv_bfloat16 g_Wkt[(size_t)DIM*DIM];
__device__ float g_num[2][BATCH*SEQ];
__device__ float g_den[2][BATCH*SEQ];

// ---------------- helpers ----------------------------------------------------
#define SWZ(o) ((o) ^ (((o) >> 3) & 0x70))

__device__ __forceinline__ uint32_t smem_u32(const void* p) {
    uint32_t a;
    asm("{ .reg .u64 t; cvta.to.shared.u64 t, %1; cvt.u32.u64 %0, t; }"
        : "=r"(a) : "l"(p));
    return a;
}
__device__ __forceinline__ void ldsm_x4(uint32_t* r, uint32_t addr) {
    asm volatile("ldmatrix.sync.aligned.m8n8.x4.shared.b16 {%0,%1,%2,%3}, [%4];"
                 : "=r"(r[0]), "=r"(r[1]), "=r"(r[2]), "=r"(r[3]) : "r"(addr));
}
__device__ __forceinline__ void mma_bf16(float* c, const uint32_t* a,
                                         uint32_t b0, uint32_t b1) {
    asm volatile(
        "mma.sync.aligned.m16n8k16.row.col.f32.bf16.bf16.f32 "
        "{%0,%1,%2,%3}, {%4,%5,%6,%7}, {%8,%9}, {%0,%1,%2,%3};"
        : "+f"(c[0]), "+f"(c[1]), "+f"(c[2]), "+f"(c[3])
        : "r"(a[0]), "r"(a[1]), "r"(a[2]), "r"(a[3]), "r"(b0), "r"(b1));
}
__device__ __forceinline__ float fast_tanh(float x) {
    float y; asm("tanh.approx.f32 %0, %1;" : "=f"(y) : "f"(x)); return y;
}

// mbarrier + bulk-copy primitives (Hopper+ PTX; valid on plain sm_103)
#define MBARRIER_INIT(addr, cnt) \
    asm volatile("mbarrier.init.shared.b64 [%0], %1;" :: "r"(addr), "r"(cnt) : "memory")
#define MBARRIER_EXPECT_TX(addr, bytes) \
    asm volatile("mbarrier.arrive.expect_tx.shared.b64 _, [%0], %1;" \
                 :: "r"(addr), "r"(bytes) : "memory")
#define MBARRIER_WAIT_PARITY(mbar, par) do { \
    uint32_t _m = (uint32_t)(mbar), _p = (uint32_t)(par), _d; \
    asm volatile("{\n\t.reg .pred p;\n\t" \
        "mbarrier.try_wait.parity.acquire.cta.shared::cta.b64 p, [%1], %2;\n\t" \
        "selp.b32 %0, 1, 0, p;\n\t}" : "=r"(_d) : "r"(_m), "r"(_p) : "memory"); \
    if (!_d) { \
        asm volatile("{\n\t.reg .pred P1;\n\t" \
            "WL_%=:\n\t" \
            "mbarrier.try_wait.parity.acquire.cta.shared::cta.b64 P1, [%0], %1, 0x989680;\n\t" \
            "@P1 bra.uni WD_%=;\n\t" \
            "bra.uni WL_%=;\n\t" \
            "WD_%=:\n\t}" :: "r"(_m), "r"(_p) : "memory"); \
    } \
} while (0)
__device__ __forceinline__ void bulk_g2s(uint32_t dst, const void* src,
                                         uint32_t bytes, uint32_t mbar) {
    asm volatile(
        "cp.async.bulk.shared::cluster.global.mbarrier::complete_tx::bytes "
        "[%0], [%1], %2, [%3];"
        :: "r"(dst), "l"(src), "r"(bytes), "r"(mbar) : "memory");
}

// 128x128x64 chunk MMA on SW128-swizzled tiles (128B rows).
// Uses acc[2][8][4], aoffp0, aoffp1, boffp0 (pre-swizzle offsets) from scope.
#define CHUNK_MMA_SW(AsX, BsX) do { \
    _Pragma("unroll") \
    for (int ks = 0; ks < 4; ks++) { \
        uint32_t a0[4], a1[4], bmA[4], bmB[4]; \
        ldsm_x4(a0,  (AsX) + SWZ(aoffp0 + ks * 32)); \
        ldsm_x4(a1,  (AsX) + SWZ(aoffp1 + ks * 32)); \
        ldsm_x4(bmA, (BsX) + SWZ(boffp0 + ks * 32)); \
        _Pragma("unroll") \
        for (int np = 0; np < 4; np++) { \
            uint32_t* bc = (np & 1) ? bmB : bmA; \
            uint32_t* bn_ = (np & 1) ? bmA : bmB; \
            if (np < 3) \
                ldsm_x4(bn_, (BsX) + SWZ(boffp0 + (np + 1) * 2048 + ks * 32)); \
            mma_bf16(acc[0][np*2],   a0, bc[0], bc[2]); \
            mma_bf16(acc[0][np*2+1], a0, bc[1], bc[3]); \
            mma_bf16(acc[1][np*2],   a1, bc[0], bc[2]); \
            mma_bf16(acc[1][np*2+1], a1, bc[1], bc[3]); \
        } \
    } \
} while (0)

// ---------------------------------------------------------------------------
// convert: f32 row-major -> bf16 blocked SW128 tiles
// ---------------------------------------------------------------------------
__global__ void convert_bf16_2(const float* __restrict__ x1, const float* __restrict__ x2,
                               __nv_bfloat16* __restrict__ y1, __nv_bfloat16* __restrict__ y2)
{
    const float* x = blockIdx.z ? x2 : x1;
    char* y = (char*)(blockIdx.z ? y2 : y1);
    const size_t i = ((size_t)blockIdx.x * blockDim.x + threadIdx.x) * 8;
    const uint32_t m = (uint32_t)(i / DIM), k = (uint32_t)(i % DIM);
    float4 v0 = *(const float4*)(x + i);
    float4 v1 = *(const float4*)(x + i + 4);
    __nv_bfloat162 a = __floats2bfloat162_rn(v0.x, v0.y);
    __nv_bfloat162 b = __floats2bfloat162_rn(v0.z, v0.w);
    __nv_bfloat162 c = __floats2bfloat162_rn(v1.x, v1.y);
    __nv_bfloat162 d = __floats2bfloat162_rn(v1.z, v1.w);
    uint4 st; st.x = *(uint32_t*)&a; st.y = *(uint32_t*)&b;
    st.z = *(uint32_t*)&c; st.w = *(uint32_t*)&d;
    const size_t tbase = ((size_t)(m >> 7) * NCH + (k >> 6)) << 14;
    *(uint4*)(y + tbase + SWZ((m & 127) * 128 + (k & 63) * 2)) = st;
}

// transpose: W[k][n] f32 -> Wt blocked SW128 tiles over (n-tile, k-chunk)
__global__ void transpose_bf16_2(const float* __restrict__ W1, const float* __restrict__ W2,
                                 __nv_bfloat16* __restrict__ T1, __nv_bfloat16* __restrict__ T2)
{
    const float* W = blockIdx.z ? W2 : W1;
    char* Wt = (char*)(blockIdx.z ? T2 : T1);
    __shared__ float t[32][33];
    int tx = threadIdx.x, ty = threadIdx.y;
    int bk = blockIdx.y * 32, bn = blockIdx.x * 32;
#pragma unroll
    for (int j = 0; j < 4; j++)
        t[ty + j * 8][tx] = W[(size_t)(bk + ty + j * 8) * DIM + bn + tx];
    __syncthreads();
#pragma unroll
    for (int j = 0; j < 4; j++) {
        const uint32_t n = bn + ty + j * 8, k = bk + tx;
        const size_t tbase = ((size_t)(n >> 7) * NCH + (k >> 6)) << 14;
        *(__nv_bfloat16*)(Wt + tbase + SWZ((n & 127) * 128 + (k & 63) * 2)) =
            __float2bfloat16(t[tx][ty + j * 8]);
    }
}

__global__ void finalize(const float* __restrict__ n0, const float* __restrict__ n1,
                         const float* __restrict__ d0, const float* __restrict__ d1,
                         float* __restrict__ out)
{
    const int i = blockIdx.x * blockDim.x + threadIdx.x;
    out[i] = (n0[i] + n1[i]) / (d0[i] + d1[i] + 1e-7f);
}

// ---------------------------------------------------------------------------
// Phase 1 (merged Q & K via blockIdx.z): blocked-tile GEMM, bulk-copy loads.
// CTA 128x128, K chunks of 64, ring-3 slots, mbarrier pipeline.
// SMEM: [8) mbars x3 | [1024) A ring 3x16K | [+48K) B ring 3x16K | bias
// ---------------------------------------------------------------------------
#define P1_SMEM (1024 + 6*TILE_BYTES + 512)

__global__ void __launch_bounds__(256, 2)
gemm_bias_mma(const __nv_bfloat16* __restrict__ A1, const __nv_bfloat16* __restrict__ A2,
              const __nv_bfloat16* __restrict__ B1, const __nv_bfloat16* __restrict__ B2,
              const float* __restrict__ bias1, const float* __restrict__ bias2,
              __nv_bfloat16* __restrict__ O1, __nv_bfloat16* __restrict__ O2)
{
    extern __shared__ __align__(16) char smem[];
    const uint32_t sb = smem_u32(smem);
    const int tid = threadIdx.x, lane = tid & 31, wid = tid >> 5;
    const int wm = wid >> 1, wn = wid & 1;
    const int n0 = blockIdx.x * 128, m0 = blockIdx.y * 128;
    const int z = blockIdx.z;

    const char* A  = (const char*)(z ? A2 : A1);
    const char* Bt = (const char*)(z ? B2 : B1);
    const float* bias = z ? bias2 : bias1;
    char* Out = (char*)(z ? O2 : O1);

    const uint32_t MB = sb + 8;
    float* bias_s = (float*)(smem + 1024 + 6*TILE_BYTES);
    if (tid == 0) {
        MBARRIER_INIT(MB + 0, 1); MBARRIER_INIT(MB + 8, 1); MBARRIER_INIT(MB + 16, 1);
    }
    if (tid < 128) bias_s[tid] = bias[n0 + tid];
    __syncthreads();

    // pre-swizzle ldsm offsets
    const uint32_t seg = (uint32_t)(lane >> 4) * 16;
    const uint32_t aoffp0 = (uint32_t)(wm * 32 + (lane & 15)) * 128 + seg;
    const uint32_t aoffp1 = aoffp0 + 16 * 128;
    const uint32_t boffp0 = (uint32_t)(wn * 64 + (lane & 15)) * 128 + seg;

#define ASLOT(s) (sb + 1024 + (s) * TILE_BYTES)
#define BSLOT(s) (sb + 1024 + 3*TILE_BYTES + (s) * TILE_BYTES)
#define GISSUE(cc) do { \
        const int _s = (cc) % 3; \
        MBARRIER_EXPECT_TX(MB + 8 * _s, 2 * TILE_BYTES); \
        bulk_g2s(ASLOT(_s), A  + (((size_t)(m0 >> 7) * NCH + (cc)) << 14), \
                 TILE_BYTES, MB + 8 * _s); \
        bulk_g2s(BSLOT(_s), Bt + (((size_t)(n0 >> 7) * NCH + (cc)) << 14), \
                 TILE_BYTES, MB + 8 * _s); \
    } while (0)

    float acc[2][8][4];
#pragma unroll
    for (int i = 0; i < 2; i++)
#pragma unroll
        for (int j = 0; j < 8; j++)
#pragma unroll
            for (int q = 0; q < 4; q++) acc[i][j][q] = 0.f;

    if (tid == 0) { GISSUE(0); GISSUE(1); GISSUE(2); }

    int ph[3] = {0, 0, 0};
    for (int c = 0; c < NCH; c++) {
        const int s = c % 3;
        MBARRIER_WAIT_PARITY(MB + 8 * s, ph[s]); ph[s] ^= 1;
        CHUNK_MMA_SW(ASLOT(s), BSLOT(s));
        __syncthreads();
        if (c + 3 < NCH && tid == 0) GISSUE(c + 3);
    }
#undef GISSUE
#undef ASLOT
#undef BSLOT

    // epilogue: + bias, bf16 store into blocked SW128 layout
#pragma unroll
    for (int mt = 0; mt < 2; mt++) {
        const uint32_t row0 = (uint32_t)(wm * 32 + mt * 16 + (lane >> 2));
#pragma unroll
        for (int nt = 0; nt < 8; nt++) {
            const int nl = wn * 64 + nt * 8 + (lane & 3) * 2;
            const float b0 = bias_s[nl], b1 = bias_s[nl + 1];
            __nv_bfloat162 p0 = __floats2bfloat162_rn(acc[mt][nt][0] + b0, acc[mt][nt][1] + b1);
            __nv_bfloat162 p1 = __floats2bfloat162_rn(acc[mt][nt][2] + b0, acc[mt][nt][3] + b1);
            const size_t tb = ((size_t)(m0 >> 7) * NCH + (n0 >> 6) + wn) << 14;
            const uint32_t col2 = (uint32_t)(nt * 8 + (lane & 3) * 2) * 2;
            *(uint32_t*)(Out + tb + SWZ(row0 * 128 + col2))       = *(uint32_t*)&p0;
            *(uint32_t*)(Out + tb + SWZ((row0 + 8) * 128 + col2)) = *(uint32_t*)&p1;
        }
    }
}

// ---------------------------------------------------------------------------
// Phase 2 (R7 structure): per (t-block 128, batch, s-half): 8 s-tiles of 128,
// 96-chunk ring-3 bulk-copy pipeline, partial num/den per s-half + finalize.
// SMEM: [8) mbars x3 | [64) num | [576) den | [2048) Q ring 3x16K | K ring 3x16K
// ---------------------------------------------------------------------------
#define P2_SMEM (2048 + 6*TILE_BYTES)
#define GTOT (8*NCH)   // 96

__global__ void __launch_bounds__(256, 2)
attn_mma(const __nv_bfloat16* __restrict__ Q, const __nv_bfloat16* __restrict__ K,
         float* __restrict__ gnum0, float* __restrict__ gnum1,
         float* __restrict__ gden0, float* __restrict__ gden1)
{
    extern __shared__ __align__(16) char smem[];
    const uint32_t sb = smem_u32(smem);
    float* num_sh = (float*)(smem + 64);
    float* den_sh = (float*)(smem + 576);
    const int tid = threadIdx.x, lane = tid & 31, wid = tid >> 5;
    const int wm = wid >> 1, wn = wid & 1;
    const int t0 = blockIdx.x * 128, b = blockIdx.y, sh = blockIdx.z;
    const uint32_t MB = sb + 8;

    const char* Qb = (const char*)Q;
    const char* Kb = (const char*)K;
    const int ktile = b * 16 + blockIdx.x;           // K block tile index
    const int qtile0 = b * 16 + sh * 8;              // first Q tile of this s-half

    if (tid == 0) {
        MBARRIER_INIT(MB + 0, 1); MBARRIER_INIT(MB + 8, 1); MBARRIER_INIT(MB + 16, 1);
    }
    if (tid < 128) { num_sh[tid] = 0.f; den_sh[tid] = 0.f; }
    __syncthreads();

    const uint32_t seg = (uint32_t)(lane >> 4) * 16;
    const uint32_t aoffp0 = (uint32_t)(wm * 32 + (lane & 15)) * 128 + seg;
    const uint32_t aoffp1 = aoffp0 + 16 * 128;
    const uint32_t boffp0 = (uint32_t)(wn * 64 + (lane & 15)) * 128 + seg;

#define QSLOT(s) (sb + 2048 + (s) * TILE_BYTES)
#define KSLOT(s) (sb + 2048 + 3*TILE_BYTES + (s) * TILE_BYTES)
#define AISSUE(gg) do { \
        const int _st = (gg) / NCH, _cc = (gg) % NCH, _s = (gg) % 3; \
        MBARRIER_EXPECT_TX(MB + 8 * _s, 2 * TILE_BYTES); \
        bulk_g2s(QSLOT(_s), Qb + (((size_t)(qtile0 + _st) * NCH + _cc) << 14), \
                 TILE_BYTES, MB + 8 * _s); \
        bulk_g2s(KSLOT(_s), Kb + (((size_t)ktile * NCH + _cc) << 14), \
                 TILE_BYTES, MB + 8 * _s); \
    } while (0)

    float acc[2][8][4];
#pragma unroll
    for (int i = 0; i < 2; i++)
#pragma unroll
        for (int j = 0; j < 8; j++)
#pragma unroll
            for (int q = 0; q < 4; q++) acc[i][j][q] = 0.f;

    if (tid == 0) { AISSUE(0); AISSUE(1); AISSUE(2); }

    int ph[3] = {0, 0, 0};
    for (int g = 0; g < GTOT; g++) {
        const int s = g % 3;
        MBARRIER_WAIT_PARITY(MB + 8 * s, ph[s]); ph[s] ^= 1;
        CHUNK_MMA_SW(QSLOT(s), KSLOT(s));

        if ((g % NCH) == NCH - 1) {
            // s-tile complete: e = exp(tanh(qk)); reduce over s into num/den per t
#pragma unroll
            for (int nt = 0; nt < 8; nt++) {
                float vn0 = 0.f, vn1 = 0.f, vd0 = 0.f, vd1 = 0.f;
#pragma unroll
                for (int mt = 0; mt < 2; mt++) {
                    const float q0 = acc[mt][nt][0], q1 = acc[mt][nt][1];
                    const float q2 = acc[mt][nt][2], q3 = acc[mt][nt][3];
                    const float e0 = __expf(fast_tanh(q0));
                    const float e1 = __expf(fast_tanh(q1));
                    const float e2 = __expf(fast_tanh(q2));
                    const float e3 = __expf(fast_tanh(q3));
                    vn0 += e0 * q0 + e2 * q2;  vd0 += e0 + e2;
                    vn1 += e1 * q1 + e3 * q3;  vd1 += e1 + e3;
                }
#pragma unroll
                for (int o = 4; o <= 16; o <<= 1) {
                    vn0 += __shfl_xor_sync(0xFFFFFFFFu, vn0, o);
                    vn1 += __shfl_xor_sync(0xFFFFFFFFu, vn1, o);
                    vd0 += __shfl_xor_sync(0xFFFFFFFFu, vd0, o);
                    vd1 += __shfl_xor_sync(0xFFFFFFFFu, vd1, o);
                }
                if (lane < 4) {
                    const int col = wn * 64 + nt * 8 + lane * 2;
                    atomicAdd(&num_sh[col],     vn0);
                    atomicAdd(&num_sh[col + 1], vn1);
                    atomicAdd(&den_sh[col],     vd0);
                    atomicAdd(&den_sh[col + 1], vd1);
                }
            }
#pragma unroll
            for (int i = 0; i < 2; i++)
#pragma unroll
                for (int j = 0; j < 8; j++)
#pragma unroll
                    for (int q = 0; q < 4; q++) acc[i][j][q] = 0.f;
        }

        __syncthreads();   // all warps done reading slot s before refill
        if (g + 3 < GTOT && tid == 0) AISSUE(g + 3);
    }
#undef AISSUE
#undef QSLOT
#undef KSLOT

    if (tid < 128) {
        float* gn = sh ? gnum1 : gnum0;
        float* gd = sh ? gden1 : gden0;
        gn[(size_t)b * SEQ + t0 + tid] = num_sh[tid];
        gd[(size_t)b * SEQ + t0 + tid] = den_sh[tid];
    }
}

// ---------------------------------------------------------------------------
extern "C" void kernel_launch(void* const* d_in, const int* in_sizes, int n_in,
                              void* d_out, int out_size)
{
    const float* x1 = (const float*)d_in[0];
    const float* x2 = (const float*)d_in[1];
    const float* Wq = (const float*)d_in[2];
    const float* bq = (const float*)d_in[3];
    const float* Wk = (const float*)d_in[4];
    const float* bk = (const float*)d_in[5];
    float* out = (float*)d_out;

    __nv_bfloat16 *X1b, *X2b, *Qp, *Kp, *Wqt, *Wkt;
    float *gnum, *gden;
    cudaGetSymbolAddress((void**)&X1b, g_X1b);
    cudaGetSymbolAddress((void**)&X2b, g_X2b);
    cudaGetSymbolAddress((void**)&Qp,  g_Q);
    cudaGetSymbolAddress((void**)&Kp,  g_K);
    cudaGetSymbolAddress((void**)&Wqt, g_Wqt);
    cudaGetSymbolAddress((void**)&Wkt, g_Wkt);
    cudaGetSymbolAddress((void**)&gnum, g_num);
    cudaGetSymbolAddress((void**)&gden, g_den);
    float* gnum1 = gnum + BATCH*SEQ;
    float* gden1 = gden + BATCH*SEQ;

    cudaFuncSetAttribute(gemm_bias_mma, cudaFuncAttributeMaxDynamicSharedMemorySize, P1_SMEM);
    cudaFuncSetAttribute(attn_mma,      cudaFuncAttributeMaxDynamicSharedMemorySize, P2_SMEM);

    const int nconv = (int)(((size_t)MTOT * DIM / 8) / 256);   // 6144 blocks
    convert_bf16_2<<<dim3(nconv, 1, 2), 256>>>(x1, x2, X1b, X2b);

    dim3 tgrid(DIM / 32, DIM / 32, 2);
    transpose_bf16_2<<<tgrid, dim3(32, 8)>>>(Wq, Wk, Wqt, Wkt);

    dim3 ggrid(DIM / 128, MTOT / 128, 2);   // (6, 128, 2) = 1536 CTAs
    gemm_bias_mma<<<ggrid, 256, P1_SMEM>>>(X1b, X2b, Wqt, Wkt, bq, bk, Qp, Kp);

    dim3 agrid(SEQ / 128, BATCH, 2);        // (16, 8, 2) = 256 CTAs
    attn_mma<<<agrid, 256, P2_SMEM>>>(Qp, Kp, gnum, gnum1, gden, gden1);

    finalize<<<BATCH*SEQ/256, 256>>>(gnum, gnum1, gden, gden1, out);
}

// round 12
// speedup vs baseline: 1.6865x; 1.0013x over previous
#include <cuda_runtime.h>
#include <cuda_bf16.h>
#include <cstdint>
#include <cstddef>

#define BATCH 8
#define SEQ   2048
#define DIM   768
#define MTOT  (BATCH*SEQ)   // 16384
#define NCH   12            // 768 / 64 k-chunks
#define TILE_BYTES 16384    // one (128-row x 64-k) bf16 tile, SW128-swizzled

// ---------------- scratch (no dynamic allocation allowed) -------------------
// All operand buffers use a blocked layout: [tile(128 rows)][chunk(64 k)] of
// contiguous 16KB SW128-swizzled tiles, so loads are single bulk copies.
__device__ __align__(256) __nv_bfloat16 g_X1b[(size_t)MTOT*DIM];
__device__ __align__(256) __nv_bfloat16 g_X2b[(size_t)MTOT*DIM];
__device__ __align__(256) __nv_bfloat16 g_Q  [(size_t)MTOT*DIM];
__device__ __align__(256) __nv_bfloat16 g_K  [(size_t)MTOT*DIM];
__device__ __align__(256) __nv_bfloat16 g_Wqt[(size_t)DIM*DIM];
__device__ __align__(256) __nv_bfloat16 g_Wkt[(size_t)DIM*DIM];
__device__ float g_num[2][BATCH*SEQ];
__device__ float g_den[2][BATCH*SEQ];

// ---------------- helpers ----------------------------------------------------
#define SWZ(o) ((o) ^ (((o) >> 3) & 0x70))

__device__ __forceinline__ uint32_t smem_u32(const void* p) {
    uint32_t a;
    asm("{ .reg .u64 t; cvta.to.shared.u64 t, %1; cvt.u32.u64 %0, t; }"
        : "=r"(a) : "l"(p));
    return a;
}
__device__ __forceinline__ void ldsm_x4(uint32_t* r, uint32_t addr) {
    asm volatile("ldmatrix.sync.aligned.m8n8.x4.shared.b16 {%0,%1,%2,%3}, [%4];"
                 : "=r"(r[0]), "=r"(r[1]), "=r"(r[2]), "=r"(r[3]) : "r"(addr));
}
__device__ __forceinline__ void mma_bf16(float* c, const uint32_t* a,
                                         uint32_t b0, uint32_t b1) {
    asm volatile(
        "mma.sync.aligned.m16n8k16.row.col.f32.bf16.bf16.f32 "
        "{%0,%1,%2,%3}, {%4,%5,%6,%7}, {%8,%9}, {%0,%1,%2,%3};"
        : "+f"(c[0]), "+f"(c[1]), "+f"(c[2]), "+f"(c[3])
        : "r"(a[0]), "r"(a[1]), "r"(a[2]), "r"(a[3]), "r"(b0), "r"(b1));
}
__device__ __forceinline__ float fast_tanh(float x) {
    float y; asm("tanh.approx.f32 %0, %1;" : "=f"(y) : "f"(x)); return y;
}

// mbarrier + bulk-copy primitives (Hopper+ PTX; valid on plain sm_103)
#define MBARRIER_INIT(addr, cnt) \
    asm volatile("mbarrier.init.shared.b64 [%0], %1;" :: "r"(addr), "r"(cnt) : "memory")
#define MBARRIER_EXPECT_TX(addr, bytes) \
    asm volatile("mbarrier.arrive.expect_tx.shared.b64 _, [%0], %1;" \
                 :: "r"(addr), "r"(bytes) : "memory")
#define MBARRIER_WAIT_PARITY(mbar, par) do { \
    uint32_t _m = (uint32_t)(mbar), _p = (uint32_t)(par), _d; \
    asm volatile("{\n\t.reg .pred p;\n\t" \
        "mbarrier.try_wait.parity.acquire.cta.shared::cta.b64 p, [%1], %2;\n\t" \
        "selp.b32 %0, 1, 0, p;\n\t}" : "=r"(_d) : "r"(_m), "r"(_p) : "memory"); \
    if (!_d) { \
        asm volatile("{\n\t.reg .pred P1;\n\t" \
            "WL_%=:\n\t" \
            "mbarrier.try_wait.parity.acquire.cta.shared::cta.b64 P1, [%0], %1, 0x989680;\n\t" \
            "@P1 bra.uni WD_%=;\n\t" \
            "bra.uni WL_%=;\n\t" \
            "WD_%=:\n\t}" :: "r"(_m), "r"(_p) : "memory"); \
    } \
} while (0)
__device__ __forceinline__ void bulk_g2s(uint32_t dst, const void* src,
                                         uint32_t bytes, uint32_t mbar) {
    asm volatile(
        "cp.async.bulk.shared::cluster.global.mbarrier::complete_tx::bytes "
        "[%0], [%1], %2, [%3];"
        :: "r"(dst), "l"(src), "r"(bytes), "r"(mbar) : "memory");
}

// 128x128x64 chunk MMA on SW128-swizzled tiles, XOR-folded addressing.
// Slot bases are >=1KB aligned and aoffp/boffp have bits 5-6 clear, so
// base + SWZ(off + ks*32 + np*2048) == (base + SWZ(off) + np*2048) ^ (ks*32).
// Uses acc[2][8][4], aswz0, aswz1, bswz0 (pre-swizzled offsets) from scope.
#define CHUNK_MMA_SW(AsX, BsX) do { \
    const uint32_t _Ab0 = (AsX) + aswz0; \
    const uint32_t _Ab1 = (AsX) + aswz1; \
    const uint32_t _Bb  = (BsX) + bswz0; \
    _Pragma("unroll") \
    for (int ks = 0; ks < 4; ks++) { \
        const uint32_t _kx = ks * 32; \
        uint32_t a0[4], a1[4], bmA[4], bmB[4]; \
        ldsm_x4(a0,  _Ab0 ^ _kx); \
        ldsm_x4(a1,  _Ab1 ^ _kx); \
        ldsm_x4(bmA, _Bb ^ _kx); \
        _Pragma("unroll") \
        for (int np = 0; np < 4; np++) { \
            uint32_t* bc = (np & 1) ? bmB : bmA; \
            uint32_t* bn_ = (np & 1) ? bmA : bmB; \
            if (np < 3) \
                ldsm_x4(bn_, (_Bb + (np + 1) * 2048) ^ _kx); \
            mma_bf16(acc[0][np*2],   a0, bc[0], bc[2]); \
            mma_bf16(acc[0][np*2+1], a0, bc[1], bc[3]); \
            mma_bf16(acc[1][np*2],   a1, bc[0], bc[2]); \
            mma_bf16(acc[1][np*2+1], a1, bc[1], bc[3]); \
        } \
    } \
} while (0)

// ---------------------------------------------------------------------------
// convert: f32 row-major -> bf16 blocked SW128 tiles
// ---------------------------------------------------------------------------
__global__ void convert_bf16_2(const float* __restrict__ x1, const float* __restrict__ x2,
                               __nv_bfloat16* __restrict__ y1, __nv_bfloat16* __restrict__ y2)
{
    const float* x = blockIdx.z ? x2 : x1;
    char* y = (char*)(blockIdx.z ? y2 : y1);
    const size_t i = ((size_t)blockIdx.x * blockDim.x + threadIdx.x) * 8;
    const uint32_t m = (uint32_t)(i / DIM), k = (uint32_t)(i % DIM);
    float4 v0 = *(const float4*)(x + i);
    float4 v1 = *(const float4*)(x + i + 4);
    __nv_bfloat162 a = __floats2bfloat162_rn(v0.x, v0.y);
    __nv_bfloat162 b = __floats2bfloat162_rn(v0.z, v0.w);
    __nv_bfloat162 c = __floats2bfloat162_rn(v1.x, v1.y);
    __nv_bfloat162 d = __floats2bfloat162_rn(v1.z, v1.w);
    uint4 st; st.x = *(uint32_t*)&a; st.y = *(uint32_t*)&b;
    st.z = *(uint32_t*)&c; st.w = *(uint32_t*)&d;
    const size_t tbase = ((size_t)(m >> 7) * NCH + (k >> 6)) << 14;
    *(uint4*)(y + tbase + SWZ((m & 127) * 128 + (k & 63) * 2)) = st;
}

// transpose: W[k][n] f32 -> Wt blocked SW128 tiles over (n-tile, k-chunk)
__global__ void transpose_bf16_2(const float* __restrict__ W1, const float* __restrict__ W2,
                                 __nv_bfloat16* __restrict__ T1, __nv_bfloat16* __restrict__ T2)
{
    const float* W = blockIdx.z ? W2 : W1;
    char* Wt = (char*)(blockIdx.z ? T2 : T1);
    __shared__ float t[32][33];
    int tx = threadIdx.x, ty = threadIdx.y;
    int bk = blockIdx.y * 32, bn = blockIdx.x * 32;
#pragma unroll
    for (int j = 0; j < 4; j++)
        t[ty + j * 8][tx] = W[(size_t)(bk + ty + j * 8) * DIM + bn + tx];
    __syncthreads();
#pragma unroll
    for (int j = 0; j < 4; j++) {
        const uint32_t n = bn + ty + j * 8, k = bk + tx;
        const size_t tbase = ((size_t)(n >> 7) * NCH + (k >> 6)) << 14;
        *(__nv_bfloat16*)(Wt + tbase + SWZ((n & 127) * 128 + (k & 63) * 2)) =
            __float2bfloat16(t[tx][ty + j * 8]);
    }
}

__global__ void finalize(const float* __restrict__ n0, const float* __restrict__ n1,
                         const float* __restrict__ d0, const float* __restrict__ d1,
                         float* __restrict__ out)
{
    const int i = blockIdx.x * blockDim.x + threadIdx.x;
    out[i] = (n0[i] + n1[i]) / (d0[i] + d1[i] + 1e-7f);
}

// ---------------------------------------------------------------------------
// Phase 1 (merged Q & K via blockIdx.z): blocked-tile GEMM, bulk-copy loads.
// CTA 128x128, K chunks of 64, ring-3 slots, mbarrier pipeline.
// SMEM: [8) mbars x3 | [1024) A ring 3x16K | [+48K) B ring 3x16K | bias
// ---------------------------------------------------------------------------
#define P1_SMEM (1024 + 6*TILE_BYTES + 512)

__global__ void __launch_bounds__(256, 2)
gemm_bias_mma(const __nv_bfloat16* __restrict__ A1, const __nv_bfloat16* __restrict__ A2,
              const __nv_bfloat16* __restrict__ B1, const __nv_bfloat16* __restrict__ B2,
              const float* __restrict__ bias1, const float* __restrict__ bias2,
              __nv_bfloat16* __restrict__ O1, __nv_bfloat16* __restrict__ O2)
{
    extern __shared__ __align__(16) char smem[];
    const uint32_t sb = smem_u32(smem);
    const int tid = threadIdx.x, lane = tid & 31, wid = tid >> 5;
    const int wm = wid >> 1, wn = wid & 1;
    const int n0 = blockIdx.x * 128, m0 = blockIdx.y * 128;
    const int z = blockIdx.z;

    const char* A  = (const char*)(z ? A2 : A1);
    const char* Bt = (const char*)(z ? B2 : B1);
    const float* bias = z ? bias2 : bias1;
    char* Out = (char*)(z ? O2 : O1);

    const uint32_t MB = sb + 8;
    float* bias_s = (float*)(smem + 1024 + 6*TILE_BYTES);
    if (tid == 0) {
        MBARRIER_INIT(MB + 0, 1); MBARRIER_INIT(MB + 8, 1); MBARRIER_INIT(MB + 16, 1);
    }
    if (tid < 128) bias_s[tid] = bias[n0 + tid];
    __syncthreads();

    // pre-swizzled ldsm offsets (XOR-folded addressing in CHUNK_MMA_SW)
    const uint32_t seg = (uint32_t)(lane >> 4) * 16;
    const uint32_t aoffp0 = (uint32_t)(wm * 32 + (lane & 15)) * 128 + seg;
    const uint32_t aswz0 = SWZ(aoffp0);
    const uint32_t aswz1 = SWZ(aoffp0 + 16 * 128);
    const uint32_t bswz0 = SWZ((uint32_t)(wn * 64 + (lane & 15)) * 128 + seg);

#define ASLOT(s) (sb + 1024 + (s) * TILE_BYTES)
#define BSLOT(s) (sb + 1024 + 3*TILE_BYTES + (s) * TILE_BYTES)
#define GISSUE(cc) do { \
        const int _s = (cc) % 3; \
        MBARRIER_EXPECT_TX(MB + 8 * _s, 2 * TILE_BYTES); \
        bulk_g2s(ASLOT(_s), A  + (((size_t)(m0 >> 7) * NCH + (cc)) << 14), \
                 TILE_BYTES, MB + 8 * _s); \
        bulk_g2s(BSLOT(_s), Bt + (((size_t)(n0 >> 7) * NCH + (cc)) << 14), \
                 TILE_BYTES, MB + 8 * _s); \
    } while (0)

    float acc[2][8][4];
#pragma unroll
    for (int i = 0; i < 2; i++)
#pragma unroll
        for (int j = 0; j < 8; j++)
#pragma unroll
            for (int q = 0; q < 4; q++) acc[i][j][q] = 0.f;

    if (tid == 0) { GISSUE(0); GISSUE(1); GISSUE(2); }

    int ph[3] = {0, 0, 0};
    for (int c = 0; c < NCH; c++) {
        const int s = c % 3;
        MBARRIER_WAIT_PARITY(MB + 8 * s, ph[s]); ph[s] ^= 1;
        CHUNK_MMA_SW(ASLOT(s), BSLOT(s));
        __syncthreads();
        if (c + 3 < NCH && tid == 0) GISSUE(c + 3);
    }
#undef GISSUE
#undef ASLOT
#undef BSLOT

    // epilogue: + bias, bf16 store into blocked SW128 layout
#pragma unroll
    for (int mt = 0; mt < 2; mt++) {
        const uint32_t row0 = (uint32_t)(wm * 32 + mt * 16 + (lane >> 2));
#pragma unroll
        for (int nt = 0; nt < 8; nt++) {
            const int nl = wn * 64 + nt * 8 + (lane & 3) * 2;
            const float b0 = bias_s[nl], b1 = bias_s[nl + 1];
            __nv_bfloat162 p0 = __floats2bfloat162_rn(acc[mt][nt][0] + b0, acc[mt][nt][1] + b1);
            __nv_bfloat162 p1 = __floats2bfloat162_rn(acc[mt][nt][2] + b0, acc[mt][nt][3] + b1);
            const size_t tb = ((size_t)(m0 >> 7) * NCH + (n0 >> 6) + wn) << 14;
            const uint32_t col2 = (uint32_t)(nt * 8 + (lane & 3) * 2) * 2;
            *(uint32_t*)(Out + tb + SWZ(row0 * 128 + col2))       = *(uint32_t*)&p0;
            *(uint32_t*)(Out + tb + SWZ((row0 + 8) * 128 + col2)) = *(uint32_t*)&p1;
        }
    }
}

// ---------------------------------------------------------------------------
// Phase 2: per (t-block 128, batch, s-half): 8 s-tiles of 128,
// 96-chunk ring-3 bulk-copy pipeline, partial num/den per s-half + finalize.
// SMEM: [8) mbars x3 | [64) num | [576) den | [2048) Q ring 3x16K | K ring 3x16K
// ---------------------------------------------------------------------------
#define P2_SMEM (2048 + 6*TILE_BYTES)
#define GTOT (8*NCH)   // 96

__global__ void __launch_bounds__(256, 2)
attn_mma(const __nv_bfloat16* __restrict__ Q, const __nv_bfloat16* __restrict__ K,
         float* __restrict__ gnum0, float* __restrict__ gnum1,
         float* __restrict__ gden0, float* __restrict__ gden1)
{
    extern __shared__ __align__(16) char smem[];
    const uint32_t sb = smem_u32(smem);
    float* num_sh = (float*)(smem + 64);
    float* den_sh = (float*)(smem + 576);
    const int tid = threadIdx.x, lane = tid & 31, wid = tid >> 5;
    const int wm = wid >> 1, wn = wid & 1;
    const int t0 = blockIdx.x * 128, b = blockIdx.y, sh = blockIdx.z;
    const uint32_t MB = sb + 8;

    const char* Qb = (const char*)Q;
    const char* Kb = (const char*)K;
    const int ktile = b * 16 + blockIdx.x;           // K block tile index
    const int qtile0 = b * 16 + sh * 8;              // first Q tile of this s-half

    if (tid == 0) {
        MBARRIER_INIT(MB + 0, 1); MBARRIER_INIT(MB + 8, 1); MBARRIER_INIT(MB + 16, 1);
    }
    if (tid < 128) { num_sh[tid] = 0.f; den_sh[tid] = 0.f; }
    __syncthreads();

    const uint32_t seg = (uint32_t)(lane >> 4) * 16;
    const uint32_t aoffp0 = (uint32_t)(wm * 32 + (lane & 15)) * 128 + seg;
    const uint32_t aswz0 = SWZ(aoffp0);
    const uint32_t aswz1 = SWZ(aoffp0 + 16 * 128);
    const uint32_t bswz0 = SWZ((uint32_t)(wn * 64 + (lane & 15)) * 128 + seg);

#define QSLOT(s) (sb + 2048 + (s) * TILE_BYTES)
#define KSLOT(s) (sb + 2048 + 3*TILE_BYTES + (s) * TILE_BYTES)
#define AISSUE(gg) do { \
        const int _st = (gg) / NCH, _cc = (gg) % NCH, _s = (gg) % 3; \
        MBARRIER_EXPECT_TX(MB + 8 * _s, 2 * TILE_BYTES); \
        bulk_g2s(QSLOT(_s), Qb + (((size_t)(qtile0 + _st) * NCH + _cc) << 14), \
                 TILE_BYTES, MB + 8 * _s); \
        bulk_g2s(KSLOT(_s), Kb + (((size_t)ktile * NCH + _cc) << 14), \
                 TILE_BYTES, MB + 8 * _s); \
    } while (0)

    float acc[2][8][4];
#pragma unroll
    for (int i = 0; i < 2; i++)
#pragma unroll
        for (int j = 0; j < 8; j++)
#pragma unroll
            for (int q = 0; q < 4; q++) acc[i][j][q] = 0.f;

    if (tid == 0) { AISSUE(0); AISSUE(1); AISSUE(2); }

    int ph[3] = {0, 0, 0};
    for (int g = 0; g < GTOT; g++) {
        const int s = g % 3;
        MBARRIER_WAIT_PARITY(MB + 8 * s, ph[s]); ph[s] ^= 1;
        CHUNK_MMA_SW(QSLOT(s), KSLOT(s));

        if ((g % NCH) == NCH - 1) {
            // s-tile complete: e = exp(tanh(qk)); reduce over s into num/den per t
#pragma unroll
            for (int nt = 0; nt < 8; nt++) {
                float vn0 = 0.f, vn1 = 0.f, vd0 = 0.f, vd1 = 0.f;
#pragma unroll
                for (int mt = 0; mt < 2; mt++) {
                    const float q0 = acc[mt][nt][0], q1 = acc[mt][nt][1];
                    const float q2 = acc[mt][nt][2], q3 = acc[mt][nt][3];
                    const float e0 = __expf(fast_tanh(q0));
                    const float e1 = __expf(fast_tanh(q1));
                    const float e2 = __expf(fast_tanh(q2));
                    const float e3 = __expf(fast_tanh(q3));
                    vn0 += e0 * q0 + e2 * q2;  vd0 += e0 + e2;
                    vn1 += e1 * q1 + e3 * q3;  vd1 += e1 + e3;
                }
#pragma unroll
                for (int o = 4; o <= 16; o <<= 1) {
                    vn0 += __shfl_xor_sync(0xFFFFFFFFu, vn0, o);
                    vn1 += __shfl_xor_sync(0xFFFFFFFFu, vn1, o);
                    vd0 += __shfl_xor_sync(0xFFFFFFFFu, vd0, o);
                    vd1 += __shfl_xor_sync(0xFFFFFFFFu, vd1, o);
                }
                if (lane < 4) {
                    const int col = wn * 64 + nt * 8 + lane * 2;
                    atomicAdd(&num_sh[col],     vn0);
                    atomicAdd(&num_sh[col + 1], vn1);
                    atomicAdd(&den_sh[col],     vd0);
                    atomicAdd(&den_sh[col + 1], vd1);
                }
            }
#pragma unroll
            for (int i = 0; i < 2; i++)
#pragma unroll
                for (int j = 0; j < 8; j++)
#pragma unroll
                    for (int q = 0; q < 4; q++) acc[i][j][q] = 0.f;
        }

        __syncthreads();   // all warps done reading slot s before refill
        if (g + 3 < GTOT && tid == 0) AISSUE(g + 3);
    }
#undef AISSUE
#undef QSLOT
#undef KSLOT

    if (tid < 128) {
        float* gn = sh ? gnum1 : gnum0;
        float* gd = sh ? gden1 : gden0;
        gn[(size_t)b * SEQ + t0 + tid] = num_sh[tid];
        gd[(size_t)b * SEQ + t0 + tid] = den_sh[tid];
    }
}

// ---------------------------------------------------------------------------
extern "C" void kernel_launch(void* const* d_in, const int* in_sizes, int n_in,
                              void* d_out, int out_size)
{
    const float* x1 = (const float*)d_in[0];
    const float* x2 = (const float*)d_in[1];
    const float* Wq = (const float*)d_in[2];
    const float* bq = (const float*)d_in[3];
    const float* Wk = (const float*)d_in[4];
    const float* bk = (const float*)d_in[5];
    float* out = (float*)d_out;

    __nv_bfloat16 *X1b, *X2b, *Qp, *Kp, *Wqt, *Wkt;
    float *gnum, *gden;
    cudaGetSymbolAddress((void**)&X1b, g_X1b);
    cudaGetSymbolAddress((void**)&X2b, g_X2b);
    cudaGetSymbolAddress((void**)&Qp,  g_Q);
    cudaGetSymbolAddress((void**)&Kp,  g_K);
    cudaGetSymbolAddress((void**)&Wqt, g_Wqt);
    cudaGetSymbolAddress((void**)&Wkt, g_Wkt);
    cudaGetSymbolAddress((void**)&gnum, g_num);
    cudaGetSymbolAddress((void**)&gden, g_den);
    float* gnum1 = gnum + BATCH*SEQ;
    float* gden1 = gden + BATCH*SEQ;

    cudaFuncSetAttribute(gemm_bias_mma, cudaFuncAttributeMaxDynamicSharedMemorySize, P1_SMEM);
    cudaFuncSetAttribute(attn_mma,      cudaFuncAttributeMaxDynamicSharedMemorySize, P2_SMEM);

    const int nconv = (int)(((size_t)MTOT * DIM / 8) / 256);   // 6144 blocks
    convert_bf16_2<<<dim3(nconv, 1, 2), 256>>>(x1, x2, X1b, X2b);

    dim3 tgrid(DIM / 32, DIM / 32, 2);
    transpose_bf16_2<<<tgrid, dim3(32, 8)>>>(Wq, Wk, Wqt, Wkt);

    dim3 ggrid(DIM / 128, MTOT / 128, 2);   // (6, 128, 2) = 1536 CTAs
    gemm_bias_mma<<<ggrid, 256, P1_SMEM>>>(X1b, X2b, Wqt, Wkt, bq, bk, Qp, Kp);

    dim3 agrid(SEQ / 128, BATCH, 2);        // (16, 8, 2) = 256 CTAs
    attn_mma<<<agrid, 256, P2_SMEM>>>(Qp, Kp, gnum, gnum1, gden, gden1);

    finalize<<<BATCH*SEQ/256, 256>>>(gnum, gnum1, gden, gden1, out);
}

// round 13
// speedup vs baseline: 1.7731x; 1.0513x over previous
#include <cuda_runtime.h>
#include <cuda_bf16.h>
#include <cstdint>
#include <cstddef>

#define BATCH 8
#define SEQ   2048
#define DIM   768
#define MTOT  (BATCH*SEQ)   // 16384
#define NCH   12            // 768 / 64 k-chunks
#define TILE_BYTES 16384    // one (128-row x 64-k) bf16 tile, SW128-swizzled

// ---------------- scratch (no dynamic allocation allowed) -------------------
__device__ __align__(256) __nv_bfloat16 g_X1b[(size_t)MTOT*DIM];
__device__ __align__(256) __nv_bfloat16 g_X2b[(size_t)MTOT*DIM];
__device__ __align__(256) __nv_bfloat16 g_Q  [(size_t)MTOT*DIM];
__device__ __align__(256) __nv_bfloat16 g_K  [(size_t)MTOT*DIM];
__device__ __align__(256) __nv_bfloat16 g_Wqt[(size_t)DIM*DIM];
__device__ __align__(256) __nv_bfloat16 g_Wkt[(size_t)DIM*DIM];
__device__ float g_num[2][BATCH*SEQ];
__device__ float g_den[2][BATCH*SEQ];

// ---------------- helpers ----------------------------------------------------
#define SWZ(o) ((o) ^ (((o) >> 3) & 0x70))

__device__ __forceinline__ uint32_t smem_u32(const void* p) {
    uint32_t a;
    asm("{ .reg .u64 t; cvta.to.shared.u64 t, %1; cvt.u32.u64 %0, t; }"
        : "=r"(a) : "l"(p));
    return a;
}
__device__ __forceinline__ void ldsm_x4(uint32_t* r, uint32_t addr) {
    asm volatile("ldmatrix.sync.aligned.m8n8.x4.shared.b16 {%0,%1,%2,%3}, [%4];"
                 : "=r"(r[0]), "=r"(r[1]), "=r"(r[2]), "=r"(r[3]) : "r"(addr));
}
__device__ __forceinline__ void mma_bf16(float* c, const uint32_t* a,
                                         uint32_t b0, uint32_t b1) {
    asm volatile(
        "mma.sync.aligned.m16n8k16.row.col.f32.bf16.bf16.f32 "
        "{%0,%1,%2,%3}, {%4,%5,%6,%7}, {%8,%9}, {%0,%1,%2,%3};"
        : "+f"(c[0]), "+f"(c[1]), "+f"(c[2]), "+f"(c[3])
        : "r"(a[0]), "r"(a[1]), "r"(a[2]), "r"(a[3]), "r"(b0), "r"(b1));
}
__device__ __forceinline__ float fast_tanh(float x) {
    float y; asm("tanh.approx.f32 %0, %1;" : "=f"(y) : "f"(x)); return y;
}

// mbarrier + bulk-copy primitives (Hopper+ PTX; valid on plain sm_103)
#define MBARRIER_INIT(addr, cnt) \
    asm volatile("mbarrier.init.shared.b64 [%0], %1;" :: "r"(addr), "r"(cnt) : "memory")
#define MBARRIER_EXPECT_TX(addr, bytes) \
    asm volatile("mbarrier.arrive.expect_tx.shared.b64 _, [%0], %1;" \
                 :: "r"(addr), "r"(bytes) : "memory")
#define MBARRIER_ARRIVE(addr) \
    asm volatile("mbarrier.arrive.release.cta.shared.b64 _, [%0];" \
                 :: "r"(addr) : "memory")
#define MBARRIER_WAIT_PARITY(mbar, par) do { \
    uint32_t _m = (uint32_t)(mbar), _p = (uint32_t)(par), _d; \
    asm volatile("{\n\t.reg .pred p;\n\t" \
        "mbarrier.try_wait.parity.acquire.cta.shared::cta.b64 p, [%1], %2;\n\t" \
        "selp.b32 %0, 1, 0, p;\n\t}" : "=r"(_d) : "r"(_m), "r"(_p) : "memory"); \
    if (!_d) { \
        asm volatile("{\n\t.reg .pred P1;\n\t" \
            "WL_%=:\n\t" \
            "mbarrier.try_wait.parity.acquire.cta.shared::cta.b64 P1, [%0], %1, 0x989680;\n\t" \
            "@P1 bra.uni WD_%=;\n\t" \
            "bra.uni WL_%=;\n\t" \
            "WD_%=:\n\t}" :: "r"(_m), "r"(_p) : "memory"); \
    } \
} while (0)
__device__ __forceinline__ void bulk_g2s(uint32_t dst, const void* src,
                                         uint32_t bytes, uint32_t mbar) {
    asm volatile(
        "cp.async.bulk.shared::cluster.global.mbarrier::complete_tx::bytes "
        "[%0], [%1], %2, [%3];"
        :: "r"(dst), "l"(src), "r"(bytes), "r"(mbar) : "memory");
}

// 128x128x64 chunk MMA on SW128-swizzled tiles, XOR-folded addressing.
// Uses acc[2][8][4], aswz0, aswz1, bswz0 (pre-swizzled offsets) from scope.
#define CHUNK_MMA_SW(AsX, BsX) do { \
    const uint32_t _Ab0 = (AsX) + aswz0; \
    const uint32_t _Ab1 = (AsX) + aswz1; \
    const uint32_t _Bb  = (BsX) + bswz0; \
    _Pragma("unroll") \
    for (int ks = 0; ks < 4; ks++) { \
        const uint32_t _kx = ks * 32; \
        uint32_t a0[4], a1[4], bmA[4], bmB[4]; \
        ldsm_x4(a0,  _Ab0 ^ _kx); \
        ldsm_x4(a1,  _Ab1 ^ _kx); \
        ldsm_x4(bmA, _Bb ^ _kx); \
        _Pragma("unroll") \
        for (int np = 0; np < 4; np++) { \
            uint32_t* bc = (np & 1) ? bmB : bmA; \
            uint32_t* bn_ = (np & 1) ? bmA : bmB; \
            if (np < 3) \
                ldsm_x4(bn_, (_Bb + (np + 1) * 2048) ^ _kx); \
            mma_bf16(acc[0][np*2],   a0, bc[0], bc[2]); \
            mma_bf16(acc[0][np*2+1], a0, bc[1], bc[3]); \
            mma_bf16(acc[1][np*2],   a1, bc[0], bc[2]); \
            mma_bf16(acc[1][np*2+1], a1, bc[1], bc[3]); \
        } \
    } \
} while (0)

// ---------------------------------------------------------------------------
// convert: f32 row-major -> bf16 blocked SW128 tiles
// ---------------------------------------------------------------------------
__global__ void convert_bf16_2(const float* __restrict__ x1, const float* __restrict__ x2,
                               __nv_bfloat16* __restrict__ y1, __nv_bfloat16* __restrict__ y2)
{
    const float* x = blockIdx.z ? x2 : x1;
    char* y = (char*)(blockIdx.z ? y2 : y1);
    const size_t i = ((size_t)blockIdx.x * blockDim.x + threadIdx.x) * 8;
    const uint32_t m = (uint32_t)(i / DIM), k = (uint32_t)(i % DIM);
    float4 v0 = *(const float4*)(x + i);
    float4 v1 = *(const float4*)(x + i + 4);
    __nv_bfloat162 a = __floats2bfloat162_rn(v0.x, v0.y);
    __nv_bfloat162 b = __floats2bfloat162_rn(v0.z, v0.w);
    __nv_bfloat162 c = __floats2bfloat162_rn(v1.x, v1.y);
    __nv_bfloat162 d = __floats2bfloat162_rn(v1.z, v1.w);
    uint4 st; st.x = *(uint32_t*)&a; st.y = *(uint32_t*)&b;
    st.z = *(uint32_t*)&c; st.w = *(uint32_t*)&d;
    const size_t tbase = ((size_t)(m >> 7) * NCH + (k >> 6)) << 14;
    *(uint4*)(y + tbase + SWZ((m & 127) * 128 + (k & 63) * 2)) = st;
}

// transpose: W[k][n] f32 -> Wt blocked SW128 tiles over (n-tile, k-chunk)
__global__ void transpose_bf16_2(const float* __restrict__ W1, const float* __restrict__ W2,
                                 __nv_bfloat16* __restrict__ T1, __nv_bfloat16* __restrict__ T2)
{
    const float* W = blockIdx.z ? W2 : W1;
    char* Wt = (char*)(blockIdx.z ? T2 : T1);
    __shared__ float t[32][33];
    int tx = threadIdx.x, ty = threadIdx.y;
    int bk = blockIdx.y * 32, bn = blockIdx.x * 32;
#pragma unroll
    for (int j = 0; j < 4; j++)
        t[ty + j * 8][tx] = W[(size_t)(bk + ty + j * 8) * DIM + bn + tx];
    __syncthreads();
#pragma unroll
    for (int j = 0; j < 4; j++) {
        const uint32_t n = bn + ty + j * 8, k = bk + tx;
        const size_t tbase = ((size_t)(n >> 7) * NCH + (k >> 6)) << 14;
        *(__nv_bfloat16*)(Wt + tbase + SWZ((n & 127) * 128 + (k & 63) * 2)) =
            __float2bfloat16(t[tx][ty + j * 8]);
    }
}

__global__ void finalize(const float* __restrict__ n0, const float* __restrict__ n1,
                         const float* __restrict__ d0, const float* __restrict__ d1,
                         float* __restrict__ out)
{
    const int i = blockIdx.x * blockDim.x + threadIdx.x;
    out[i] = (n0[i] + n1[i]) / (d0[i] + d1[i] + 1e-7f);
}

// ---------------------------------------------------------------------------
// Phase 1 (merged Q & K via blockIdx.z): blocked-tile GEMM, bulk-copy loads.
// Ring-3 slots with full/empty mbarrier pairs — NO per-chunk __syncthreads.
// SMEM: [8) full x3 | [32) empty x3 | [1024) A ring 3x16K | B ring 3x16K | bias
// ---------------------------------------------------------------------------
#define P1_SMEM (1024 + 6*TILE_BYTES + 512)

__global__ void __launch_bounds__(256, 2)
gemm_bias_mma(const __nv_bfloat16* __restrict__ A1, const __nv_bfloat16* __restrict__ A2,
              const __nv_bfloat16* __restrict__ B1, const __nv_bfloat16* __restrict__ B2,
              const float* __restrict__ bias1, const float* __restrict__ bias2,
              __nv_bfloat16* __restrict__ O1, __nv_bfloat16* __restrict__ O2)
{
    extern __shared__ __align__(16) char smem[];
    const uint32_t sb = smem_u32(smem);
    const int tid = threadIdx.x, lane = tid & 31, wid = tid >> 5;
    const int wm = wid >> 1, wn = wid & 1;
    const int n0 = blockIdx.x * 128, m0 = blockIdx.y * 128;
    const int z = blockIdx.z;

    const char* A  = (const char*)(z ? A2 : A1);
    const char* Bt = (const char*)(z ? B2 : B1);
    const float* bias = z ? bias2 : bias1;
    char* Out = (char*)(z ? O2 : O1);

    const uint32_t MBF = sb + 8, MBE = sb + 32;
    float* bias_s = (float*)(smem + 1024 + 6*TILE_BYTES);
    if (tid == 0) {
        MBARRIER_INIT(MBF + 0, 1);   MBARRIER_INIT(MBF + 8, 1);   MBARRIER_INIT(MBF + 16, 1);
        MBARRIER_INIT(MBE + 0, 256); MBARRIER_INIT(MBE + 8, 256); MBARRIER_INIT(MBE + 16, 256);
    }
    if (tid < 128) bias_s[tid] = bias[n0 + tid];
    __syncthreads();

    const uint32_t seg = (uint32_t)(lane >> 4) * 16;
    const uint32_t aoffp0 = (uint32_t)(wm * 32 + (lane & 15)) * 128 + seg;
    const uint32_t aswz0 = SWZ(aoffp0);
    const uint32_t aswz1 = SWZ(aoffp0 + 16 * 128);
    const uint32_t bswz0 = SWZ((uint32_t)(wn * 64 + (lane & 15)) * 128 + seg);

#define ASLOT(s) (sb + 1024 + (s) * TILE_BYTES)
#define BSLOT(s) (sb + 1024 + 3*TILE_BYTES + (s) * TILE_BYTES)
#define GISSUE(cc, S) do { \
        MBARRIER_EXPECT_TX(MBF + 8 * (S), 2 * TILE_BYTES); \
        bulk_g2s(ASLOT(S), A  + (((size_t)(m0 >> 7) * NCH + (cc)) << 14), \
                 TILE_BYTES, MBF + 8 * (S)); \
        bulk_g2s(BSLOT(S), Bt + (((size_t)(n0 >> 7) * NCH + (cc)) << 14), \
                 TILE_BYTES, MBF + 8 * (S)); \
    } while (0)

    float acc[2][8][4];
#pragma unroll
    for (int i = 0; i < 2; i++)
#pragma unroll
        for (int j = 0; j < 8; j++)
#pragma unroll
            for (int q = 0; q < 4; q++) acc[i][j][q] = 0.f;

    if (tid == 0) { GISSUE(0, 0); GISSUE(1, 1); GISSUE(2, 2); }

    int phf0 = 0, phf1 = 0, phf2 = 0;
    int phe0 = 0, phe1 = 0, phe2 = 0;

#define GBODY(cc, S, PHF, PHE) do { \
        MBARRIER_WAIT_PARITY(MBF + 8 * (S), PHF); PHF ^= 1; \
        CHUNK_MMA_SW(ASLOT(S), BSLOT(S)); \
        MBARRIER_ARRIVE(MBE + 8 * (S)); \
        if ((cc) + 3 < NCH && tid == 0) { \
            MBARRIER_WAIT_PARITY(MBE + 8 * (S), PHE); PHE ^= 1; \
            GISSUE((cc) + 3, S); \
        } \
    } while (0)

#pragma unroll
    for (int c0 = 0; c0 < NCH; c0 += 3) {
        GBODY(c0,     0, phf0, phe0);
        GBODY(c0 + 1, 1, phf1, phe1);
        GBODY(c0 + 2, 2, phf2, phe2);
    }
#undef GBODY
#undef GISSUE
#undef ASLOT
#undef BSLOT

    // epilogue: + bias, bf16 store into blocked SW128 layout
#pragma unroll
    for (int mt = 0; mt < 2; mt++) {
        const uint32_t row0 = (uint32_t)(wm * 32 + mt * 16 + (lane >> 2));
#pragma unroll
        for (int nt = 0; nt < 8; nt++) {
            const int nl = wn * 64 + nt * 8 + (lane & 3) * 2;
            const float b0 = bias_s[nl], b1 = bias_s[nl + 1];
            __nv_bfloat162 p0 = __floats2bfloat162_rn(acc[mt][nt][0] + b0, acc[mt][nt][1] + b1);
            __nv_bfloat162 p1 = __floats2bfloat162_rn(acc[mt][nt][2] + b0, acc[mt][nt][3] + b1);
            const size_t tb = ((size_t)(m0 >> 7) * NCH + (n0 >> 6) + wn) << 14;
            const uint32_t col2 = (uint32_t)(nt * 8 + (lane & 3) * 2) * 2;
            *(uint32_t*)(Out + tb + SWZ(row0 * 128 + col2))       = *(uint32_t*)&p0;
            *(uint32_t*)(Out + tb + SWZ((row0 + 8) * 128 + col2)) = *(uint32_t*)&p1;
        }
    }
}

// ---------------------------------------------------------------------------
// Phase 2: per (t-block 128, batch, s-half): 8 s-tiles of 128,
// 96-chunk ring-3 pipeline with full/empty mbarriers — no mainloop syncthreads.
// SMEM: [8) full x3 | [32) empty x3 | [64) num | [576) den | [2048) rings
// ---------------------------------------------------------------------------
#define P2_SMEM (2048 + 6*TILE_BYTES)
#define GTOT (8*NCH)   // 96

__global__ void __launch_bounds__(256, 2)
attn_mma(const __nv_bfloat16* __restrict__ Q, const __nv_bfloat16* __restrict__ K,
         float* __restrict__ gnum0, float* __restrict__ gnum1,
         float* __restrict__ gden0, float* __restrict__ gden1)
{
    extern __shared__ __align__(16) char smem[];
    const uint32_t sb = smem_u32(smem);
    float* num_sh = (float*)(smem + 64);
    float* den_sh = (float*)(smem + 576);
    const int tid = threadIdx.x, lane = tid & 31, wid = tid >> 5;
    const int wm = wid >> 1, wn = wid & 1;
    const int t0 = blockIdx.x * 128, b = blockIdx.y, sh = blockIdx.z;
    const uint32_t MBF = sb + 8, MBE = sb + 32;

    const char* Qb = (const char*)Q;
    const char* Kb = (const char*)K;
    const int ktile = b * 16 + blockIdx.x;
    const int qtile0 = b * 16 + sh * 8;

    if (tid == 0) {
        MBARRIER_INIT(MBF + 0, 1);   MBARRIER_INIT(MBF + 8, 1);   MBARRIER_INIT(MBF + 16, 1);
        MBARRIER_INIT(MBE + 0, 256); MBARRIER_INIT(MBE + 8, 256); MBARRIER_INIT(MBE + 16, 256);
    }
    if (tid < 128) { num_sh[tid] = 0.f; den_sh[tid] = 0.f; }
    __syncthreads();

    const uint32_t seg = (uint32_t)(lane >> 4) * 16;
    const uint32_t aoffp0 = (uint32_t)(wm * 32 + (lane & 15)) * 128 + seg;
    const uint32_t aswz0 = SWZ(aoffp0);
    const uint32_t aswz1 = SWZ(aoffp0 + 16 * 128);
    const uint32_t bswz0 = SWZ((uint32_t)(wn * 64 + (lane & 15)) * 128 + seg);

#define QSLOT(s) (sb + 2048 + (s) * TILE_BYTES)
#define KSLOT(s) (sb + 2048 + 3*TILE_BYTES + (s) * TILE_BYTES)
#define AISSUE(gg, S) do { \
        const int _st = (gg) / NCH, _cc = (gg) % NCH; \
        MBARRIER_EXPECT_TX(MBF + 8 * (S), 2 * TILE_BYTES); \
        bulk_g2s(QSLOT(S), Qb + (((size_t)(qtile0 + _st) * NCH + _cc) << 14), \
                 TILE_BYTES, MBF + 8 * (S)); \
        bulk_g2s(KSLOT(S), Kb + (((size_t)ktile * NCH + _cc) << 14), \
                 TILE_BYTES, MBF + 8 * (S)); \
    } while (0)

    // per-tile epilogue: e = exp(tanh(qk)); reduce over s into num/den per t
#define EPI() do { \
        _Pragma("unroll") \
        for (int nt = 0; nt < 8; nt++) { \
            float vn0 = 0.f, vn1 = 0.f, vd0 = 0.f, vd1 = 0.f; \
            _Pragma("unroll") \
            for (int mt = 0; mt < 2; mt++) { \
                const float q0 = acc[mt][nt][0], q1 = acc[mt][nt][1]; \
                const float q2 = acc[mt][nt][2], q3 = acc[mt][nt][3]; \
                const float e0 = __expf(fast_tanh(q0)); \
                const float e1 = __expf(fast_tanh(q1)); \
                const float e2 = __expf(fast_tanh(q2)); \
                const float e3 = __expf(fast_tanh(q3)); \
                vn0 += e0 * q0 + e2 * q2;  vd0 += e0 + e2; \
                vn1 += e1 * q1 + e3 * q3;  vd1 += e1 + e3; \
            } \
            _Pragma("unroll") \
            for (int o = 4; o <= 16; o <<= 1) { \
                vn0 += __shfl_xor_sync(0xFFFFFFFFu, vn0, o); \
                vn1 += __shfl_xor_sync(0xFFFFFFFFu, vn1, o); \
                vd0 += __shfl_xor_sync(0xFFFFFFFFu, vd0, o); \
                vd1 += __shfl_xor_sync(0xFFFFFFFFu, vd1, o); \
            } \
            if (lane < 4) { \
                const int col = wn * 64 + nt * 8 + lane * 2; \
                atomicAdd(&num_sh[col],     vn0); \
                atomicAdd(&num_sh[col + 1], vn1); \
                atomicAdd(&den_sh[col],     vd0); \
                atomicAdd(&den_sh[col + 1], vd1); \
            } \
        } \
        _Pragma("unroll") \
        for (int i = 0; i < 2; i++) \
            _Pragma("unroll") \
            for (int j = 0; j < 8; j++) \
                _Pragma("unroll") \
                for (int q = 0; q < 4; q++) acc[i][j][q] = 0.f; \
    } while (0)

    float acc[2][8][4];
#pragma unroll
    for (int i = 0; i < 2; i++)
#pragma unroll
        for (int j = 0; j < 8; j++)
#pragma unroll
            for (int q = 0; q < 4; q++) acc[i][j][q] = 0.f;

    if (tid == 0) { AISSUE(0, 0); AISSUE(1, 1); AISSUE(2, 2); }

    int phf0 = 0, phf1 = 0, phf2 = 0;
    int phe0 = 0, phe1 = 0, phe2 = 0;

#define ABODY(gg, S, PHF, PHE, DO_EPI) do { \
        MBARRIER_WAIT_PARITY(MBF + 8 * (S), PHF); PHF ^= 1; \
        CHUNK_MMA_SW(QSLOT(S), KSLOT(S)); \
        MBARRIER_ARRIVE(MBE + 8 * (S)); \
        if (DO_EPI) EPI(); \
        if ((gg) + 3 < GTOT && tid == 0) { \
            MBARRIER_WAIT_PARITY(MBE + 8 * (S), PHE); PHE ^= 1; \
            AISSUE((gg) + 3, S); \
        } \
    } while (0)

    for (int g0 = 0; g0 < GTOT; g0 += 3) {
        ABODY(g0,     0, phf0, phe0, false);
        ABODY(g0 + 1, 1, phf1, phe1, false);
        // tiles are 12 chunks; last chunk of a tile lands at g0%12==9, slot 2
        ABODY(g0 + 2, 2, phf2, phe2, (g0 % NCH) == 9);
    }
#undef ABODY
#undef AISSUE
#undef QSLOT
#undef KSLOT
#undef EPI

    __syncthreads();
    if (tid < 128) {
        float* gn = sh ? gnum1 : gnum0;
        float* gd = sh ? gden1 : gden0;
        gn[(size_t)b * SEQ + t0 + tid] = num_sh[tid];
        gd[(size_t)b * SEQ + t0 + tid] = den_sh[tid];
    }
}

// ---------------------------------------------------------------------------
extern "C" void kernel_launch(void* const* d_in, const int* in_sizes, int n_in,
                              void* d_out, int out_size)
{
    const float* x1 = (const float*)d_in[0];
    const float* x2 = (const float*)d_in[1];
    const float* Wq = (const float*)d_in[2];
    const float* bq = (const float*)d_in[3];
    const float* Wk = (const float*)d_in[4];
    const float* bk = (const float*)d_in[5];
    float* out = (float*)d_out;

    __nv_bfloat16 *X1b, *X2b, *Qp, *Kp, *Wqt, *Wkt;
    float *gnum, *gden;
    cudaGetSymbolAddress((void**)&X1b, g_X1b);
    cudaGetSymbolAddress((void**)&X2b, g_X2b);
    cudaGetSymbolAddress((void**)&Qp,  g_Q);
    cudaGetSymbolAddress((void**)&Kp,  g_K);
    cudaGetSymbolAddress((void**)&Wqt, g_Wqt);
    cudaGetSymbolAddress((void**)&Wkt, g_Wkt);
    cudaGetSymbolAddress((void**)&gnum, g_num);
    cudaGetSymbolAddress((void**)&gden, g_den);
    float* gnum1 = gnum + BATCH*SEQ;
    float* gden1 = gden + BATCH*SEQ;

    cudaFuncSetAttribute(gemm_bias_mma, cudaFuncAttributeMaxDynamicSharedMemorySize, P1_SMEM);
    cudaFuncSetAttribute(attn_mma,      cudaFuncAttributeMaxDynamicSharedMemorySize, P2_SMEM);

    const int nconv = (int)(((size_t)MTOT * DIM / 8) / 256);   // 6144 blocks
    convert_bf16_2<<<dim3(nconv, 1, 2), 256>>>(x1, x2, X1b, X2b);

    dim3 tgrid(DIM / 32, DIM / 32, 2);
    transpose_bf16_2<<<tgrid, dim3(32, 8)>>>(Wq, Wk, Wqt, Wkt);

    dim3 ggrid(DIM / 128, MTOT / 128, 2);   // (6, 128, 2) = 1536 CTAs
    gemm_bias_mma<<<ggrid, 256, P1_SMEM>>>(X1b, X2b, Wqt, Wkt, bq, bk, Qp, Kp);

    dim3 agrid(SEQ / 128, BATCH, 2);        // (16, 8, 2) = 256 CTAs
    attn_mma<<<agrid, 256, P2_SMEM>>>(Qp, Kp, gnum, gnum1, gden, gden1);

    finalize<<<BATCH*SEQ/256, 256>>>(gnum, gnum1, gden, gden1, out);
}